// round 11
// baseline (speedup 1.0000x reference)
#include <cuda_runtime.h>
#include <cuda_fp16.h>
#include <cstdint>

// ---------------- problem constants ----------------
#define M_ 4096
#define K_ 4096
#define N_ 11008
#define G_ 128

#define KITERS 64            // K_/64 k-chunks
#define MT_ 32               // M_/128 activation tiles
#define NT_ 43               // N_/256 weight tiles
#define NTILES (NT_ * MT_)   // 1376
#define FULLS  1332          // 148 * 9 full tiles
#define HALves (NTILES - FULLS)          // 44 leftover -> 88 half tiles
#define GRID_GEMM (FULLS + 2 * HALves)   // 1420

#define A_TILE_BYTES 16384   // 128 rows (m) x 128B (64 fp16 k)
#define W_TILE_BYTES 32768   // 256 rows (n) x 128B
#define STAGE_BYTES  (A_TILE_BYTES + W_TILE_BYTES)   // 49152
#define STAGES 4
#define OFF_CTRL   (STAGES * STAGE_BYTES)            // 196608
#define OFF_FULL   (OFF_CTRL)
#define SMEM_TOTAL (OFF_CTRL + 128)

#define SWZ(off) ((off) ^ (((off) >> 3) & 0x70))

// ---------------- scratch (static device arrays: allocation-free) ----------------
__device__ __align__(1024) __half g_w[(size_t)K_ * N_];   // ~90 MB, [nt][kc][swz 256x128B]
__device__ __align__(1024) __half g_a[(size_t)M_ * K_];   // ~32 MB, [mt][kc][swz 128x128B]

// ---------------- PTX helpers (base sm_103-safe) ----------------
__device__ __forceinline__ uint32_t smem_u32(const void* p) {
    uint32_t a;
    asm("{ .reg .u64 t; cvta.to.shared.u64 t, %1; cvt.u32.u64 %0, t; }" : "=r"(a) : "l"(p));
    return a;
}

#define MB_INIT(mbar, cnt) \
    asm volatile("mbarrier.init.shared.b64 [%0], %1;" :: "r"(mbar), "r"(cnt) : "memory")

#define MB_EXPECT_TX(mbar, bytes) \
    asm volatile("mbarrier.arrive.expect_tx.shared.b64 _, [%0], %1;" :: "r"(mbar), "r"(bytes) : "memory")

#define MB_WAIT(mbar, ph) do { \
    asm volatile("{\n\t.reg .pred P;\n\t" \
        "WL%=:\n\t" \
        "mbarrier.try_wait.parity.acquire.cta.shared::cta.b64 P, [%0], %1, 0x989680;\n\t" \
        "@P bra WD%=;\n\t" \
        "bra WL%=;\n\t" \
        "WD%=:\n\t}" :: "r"(mbar), "r"(ph) : "memory"); \
} while (0)

#define BULK_G2S(dst, src, bytes, mbar) \
    asm volatile("cp.async.bulk.shared::cluster.global.mbarrier::complete_tx::bytes [%0], [%1], %2, [%3];" \
        :: "r"(dst), "l"(src), "r"(bytes), "r"(mbar) : "memory")

#define LDSM4(r0, r1, r2, r3, addr) \
    asm volatile("ldmatrix.sync.aligned.m8n8.x4.shared.b16 {%0,%1,%2,%3}, [%4];" \
        : "=r"(r0), "=r"(r1), "=r"(r2), "=r"(r3) : "r"(addr))

#define MMA16816(acc, a0, a1, a2, a3, b0, b1) \
    asm volatile("mma.sync.aligned.m16n8k16.row.col.f32.f16.f16.f32 " \
        "{%0,%1,%2,%3}, {%4,%5,%6,%7}, {%8,%9}, {%0,%1,%2,%3};" \
        : "+f"((acc)[0]), "+f"((acc)[1]), "+f"((acc)[2]), "+f"((acc)[3]) \
        : "r"(a0), "r"(a1), "r"(a2), "r"(a3), "r"(b0), "r"(b1))

#define STG_CS_V4(ptr, r0, r1, r2, r3) \
    asm volatile("st.global.cs.v4.b32 [%0], {%1,%2,%3,%4};" \
        :: "l"(ptr), "r"(r0), "r"(r1), "r"(r2), "r"(r3) : "memory")

__device__ __forceinline__ unsigned pack2(float a, float b) {
    __half2 h = __floats2half2_rn(a, b);
    return *reinterpret_cast<unsigned*>(&h);
}

// ---------------- prepass A: fp32 -> fp16, 128-row tile panels + SW128 ----------------
// grid (KITERS, MT_), 256 threads
__global__ void prep_a_kernel(const float* __restrict__ in) {
    int kc = blockIdx.x, mt = blockIdx.y, tid = threadIdx.x;
    char* dstbase = (char*)g_a + (size_t)(mt * KITERS + kc) * A_TILE_BYTES;
    int cc = tid & 7;
#pragma unroll
    for (int it = 0; it < 4; it++) {
        int r = (tid >> 3) + it * 32;                 // 0..127 (m local)
        int m = mt * 128 + r;
        int k0 = kc * 64 + cc * 8;
        const float4* p = (const float4*)(in + (size_t)m * K_ + k0);
        float4 f0 = p[0], f1 = p[1];
        uint4 v;
        v.x = pack2(f0.x, f0.y); v.y = pack2(f0.z, f0.w);
        v.z = pack2(f1.x, f1.y); v.w = pack2(f1.z, f1.w);
        *(uint4*)(dstbase + SWZ(r * 128 + cc * 16)) = v;
    }
}

// ---------------- prepass W: int4 dequant + transpose -> fp16 256-row tiles ----------------
// grid (KITERS, 86), 256 threads; each block handles 128 n-cols (half of a 256-row tile)
// q loads vectorized (int4), W writes streaming (st.global.cs)
__global__ void prep_w_kernel(const int* __restrict__ q,
                              const float* __restrict__ sc,
                              const int* __restrict__ zp) {
    __shared__ int   qs[64 * 129];
    __shared__ float scs[128];
    __shared__ float zps[128];
    int kc = blockIdx.x, nt2 = blockIdx.y, tid = threadIdx.x;
    int nt = nt2 >> 1, half = nt2 & 1;
    int g = kc >> 1;                                  // group of this 64-k chunk (G=128)
    if (tid < 128) {
        scs[tid] = sc[(size_t)g * N_ + nt2 * 128 + tid];
        zps[tid] = (float)zp[(size_t)g * N_ + nt2 * 128 + tid];
    }
    // 8192 ints = 2048 int4; 8 int4 per thread (16B-aligned: N_%4==0, base%128==0)
#pragma unroll
    for (int it = 0; it < 8; it++) {
        int e4 = tid + it * 256;                      // 0..2047
        int kl = e4 >> 5;                             // row 0..63 (32 int4 per row)
        int nl4 = e4 & 31;
        int4 v = *(const int4*)(q + (size_t)(kc * 64 + kl) * N_ + nt2 * 128 + nl4 * 4);
        int* d = &qs[kl * 129 + nl4 * 4];
        d[0] = v.x; d[1] = v.y; d[2] = v.z; d[3] = v.w;
    }
    __syncthreads();

    char* dstbase = (char*)g_w + (size_t)(nt * KITERS + kc) * W_TILE_BYTES;
    int cc = tid & 7;
#pragma unroll
    for (int it = 0; it < 4; it++) {
        int r = (tid >> 3) + it * 32;                 // 0..127 (n local within half)
        float s = scs[r], z = zps[r];
        unsigned u[4];
#pragma unroll
        for (int jj = 0; jj < 4; jj++) {
            int k0 = cc * 8 + jj * 2;
            float w0 = ((float)qs[(k0 + 0) * 129 + r] - z) * s;
            float w1 = ((float)qs[(k0 + 1) * 129 + r] - z) * s;
            u[jj] = pack2(w0, w1);
        }
        int row = half * 128 + r;                     // 0..255 (n local in tile)
        STG_CS_V4(dstbase + SWZ(row * 128 + cc * 16), u[0], u[1], u[2], u[3]);
    }
}

// ---------------- GEMM body (templated on half-tile mode) ----------------
// HALF=false: CTA 128(M) x 256(N), warp tile 64x64 (MI=4)
// HALF=true : CTA 128(M) x 128(N), warp tile 32x64 (MI=2); W half row-slice
// Sync: tid0 mbarrier-waits, bar.sync hands off; consumed-stage proof = all warps at bar.
template<bool HALF>
__device__ __forceinline__ void gemm_body(
    uint32_t sb, const char* wsrc, unsigned wbytes, const char* asrc,
    const float* __restrict__ bias, float* __restrict__ out,
    int nt, int mt, int halfsel)
{
    constexpr int MI = HALF ? 2 : 4;
    int tid = threadIdx.x, lane = tid & 31, wid = tid >> 5;
    int wm = HALF ? (wid & 3) : (wid & 1);
    int wn = HALF ? (wid >> 2) : (wid >> 1);

    uint32_t mb_full = sb + OFF_FULL;
    unsigned stage_tx = wbytes + (unsigned)A_TILE_BYTES;

    if (tid == 0) {
#pragma unroll
        for (int p = 0; p < STAGES; p++) {
            MB_EXPECT_TX(mb_full + 8 * p, stage_tx);
            BULK_G2S(sb + p * STAGE_BYTES,
                     wsrc + (size_t)p * W_TILE_BYTES, wbytes, mb_full + 8 * p);
            BULK_G2S(sb + p * STAGE_BYTES + W_TILE_BYTES,
                     asrc + (size_t)p * A_TILE_BYTES, (unsigned)A_TILE_BYTES, mb_full + 8 * p);
        }
    }

    // per-thread ldmatrix row bases (stage-relative)
    uint32_t a_roff[MI], b_roff[4];
    uint32_t a_swz[MI], b_swz[4];
#pragma unroll
    for (int mi = 0; mi < MI; mi++) {
        int row = wm * (16 * MI) + mi * 16 + (lane & 15);
        a_roff[mi] = W_TILE_BYTES + row * 128;        // A sits after W in stage
        a_swz[mi] = row & 7;
    }
#pragma unroll
    for (int nb = 0; nb < 4; nb++) {
        int row = wn * 64 + nb * 16 + (lane & 7) + ((lane >> 4) << 3);
        b_roff[nb] = row * 128;
        b_swz[nb] = row & 7;
    }
    uint32_t a_c = (lane >> 4);        // 0..1, A k-half within 16B cols
    uint32_t b_c = (lane >> 3) & 1;    // 0..1, B k-half

    float acc[MI][8][4];
#pragma unroll
    for (int mi = 0; mi < MI; mi++)
#pragma unroll
        for (int ni = 0; ni < 8; ni++)
#pragma unroll
            for (int e = 0; e < 4; e++) acc[mi][ni][e] = 0.f;

#pragma unroll 1
    for (int i = 0; i < KITERS; i++) {
        int s = i & (STAGES - 1);
        // single-waiter acquire + CTA-barrier handoff (others skip the TRYWAIT)
        if (tid == 0) MB_WAIT(mb_full + 8 * s, (i >> 2) & 1);
        __syncthreads();
        // all warps at the bar => chunk i-1's LDSMs are complete => stage (i-1)&3 free.
        // chunk i+3 maps to stage (i+3)&3 == (i-1)&3.
        if (tid == 0 && i >= 1 && i + 3 < KITERS) {
            int s2 = (i + 3) & (STAGES - 1);
            MB_EXPECT_TX(mb_full + 8 * s2, stage_tx);
            BULK_G2S(sb + s2 * STAGE_BYTES,
                     wsrc + (size_t)(i + 3) * W_TILE_BYTES, wbytes, mb_full + 8 * s2);
            BULK_G2S(sb + s2 * STAGE_BYTES + W_TILE_BYTES,
                     asrc + (size_t)(i + 3) * A_TILE_BYTES, (unsigned)A_TILE_BYTES, mb_full + 8 * s2);
        }
        uint32_t stg = sb + s * STAGE_BYTES;
#pragma unroll
        for (int ks = 0; ks < 4; ks++) {
            uint32_t a[MI][4], b[4][4];
#pragma unroll
            for (int mi = 0; mi < MI; mi++) {
                uint32_t addr = stg + a_roff[mi] + (((ks * 2 + a_c) ^ a_swz[mi]) << 4);
                LDSM4(a[mi][0], a[mi][1], a[mi][2], a[mi][3], addr);
            }
#pragma unroll
            for (int nb = 0; nb < 4; nb++) {
                uint32_t addr = stg + b_roff[nb] + (((ks * 2 + b_c) ^ b_swz[nb]) << 4);
                LDSM4(b[nb][0], b[nb][1], b[nb][2], b[nb][3], addr);
            }
#pragma unroll
            for (int mi = 0; mi < MI; mi++)
#pragma unroll
                for (int ni = 0; ni < 8; ni++)
                    MMA16816(acc[mi][ni],
                             a[mi][0], a[mi][1], a[mi][2], a[mi][3],
                             b[ni >> 1][(ni & 1) * 2], b[ni >> 1][(ni & 1) * 2 + 1]);
        }
    }

    // ---- epilogue: streaming coalesced float2 stores + bias ----
    int m0 = mt * 128 + wm * (16 * MI) + (lane >> 2);
    int n0 = nt * 256 + halfsel * 128 + wn * 64 + (lane & 3) * 2;
#pragma unroll
    for (int ni = 0; ni < 8; ni++) {
        int n = n0 + ni * 8;
        float2 bb = *(const float2*)(bias + n);
#pragma unroll
        for (int mi = 0; mi < MI; mi++) {
            int m = m0 + mi * 16;
            float2 v0 = make_float2(acc[mi][ni][0] + bb.x, acc[mi][ni][1] + bb.y);
            float2 v1 = make_float2(acc[mi][ni][2] + bb.x, acc[mi][ni][3] + bb.y);
            __stcs((float2*)(out + (size_t)m * N_ + n), v0);
            __stcs((float2*)(out + (size_t)(m + 8) * N_ + n), v1);
        }
    }
}

// ---------------- GEMM kernel: 1332 full tiles + 88 half tiles (tail smoothing) ----------------
// grid GRID_GEMM, 256 threads (8 warps), dyn smem SMEM_TOTAL
__global__ void __launch_bounds__(256, 1)
gemm_kernel(const float* __restrict__ bias, float* __restrict__ out) {
    extern __shared__ char smem[];
    uint32_t sb = smem_u32(smem);
    int tid = threadIdx.x;
    int bid = blockIdx.x;

    uint32_t mb_full = sb + OFF_FULL;
    if (tid == 0) {
        for (int s = 0; s < STAGES; s++) MB_INIT(mb_full + 8 * s, 1);
    }
    __syncthreads();

    if (bid < FULLS) {
        int t = bid;
        int nt = t >> 5, mt = t & 31;     // 32 consecutive bids share one W panel (L2 reuse)
        const char* wsrc = (const char*)g_w + (size_t)nt * KITERS * W_TILE_BYTES;
        const char* asrc = (const char*)g_a + (size_t)mt * KITERS * A_TILE_BYTES;
        gemm_body<false>(sb, wsrc, (unsigned)W_TILE_BYTES, asrc, bias, out, nt, mt, 0);
    } else {
        int idx = bid - FULLS;            // 0..87
        int t = FULLS + (idx >> 1);       // 1332..1375
        int halfsel = idx & 1;
        int nt = t >> 5, mt = t & 31;
        // W half-slice: rows [halfsel*128, +128) of the swizzled 256-row tile are the
        // contiguous 16KB at byte offset halfsel*16384 (swizzle is per-128B-row).
        const char* wsrc = (const char*)g_w + (size_t)nt * KITERS * W_TILE_BYTES
                         + (size_t)halfsel * (W_TILE_BYTES / 2);
        const char* asrc = (const char*)g_a + (size_t)mt * KITERS * A_TILE_BYTES;
        gemm_body<true>(sb, wsrc, (unsigned)(W_TILE_BYTES / 2), asrc, bias, out, nt, mt, halfsel);
    }
}

// ---------------- launch ----------------
extern "C" void kernel_launch(void* const* d_in, const int* in_sizes, int n_in,
                              void* d_out, int out_size) {
    const float* input   = (const float*)d_in[0];
    const int*   qweight = (const int*)d_in[1];
    const float* scales  = (const float*)d_in[2];
    const int*   qzeros  = (const int*)d_in[3];
    const float* bias    = (const float*)d_in[4];
    float* out = (float*)d_out;

    cudaFuncSetAttribute(gemm_kernel, cudaFuncAttributeMaxDynamicSharedMemorySize, SMEM_TOTAL);

    prep_a_kernel<<<dim3(KITERS, MT_), 256>>>(input);
    prep_w_kernel<<<dim3(KITERS, 86), 256>>>(qweight, scales, qzeros);
    gemm_kernel<<<GRID_GEMM, 256, SMEM_TOTAL>>>(bias, out);
}

// round 12
// speedup vs baseline: 1.1474x; 1.1474x over previous
#include <cuda_runtime.h>
#include <cuda_fp16.h>
#include <cstdint>

// ---------------- problem constants ----------------
#define M_ 4096
#define K_ 4096
#define N_ 11008
#define G_ 128

#define KITERS 64            // K_/64 k-chunks
#define MT_ 32               // M_/128 activation tiles
#define NT_ 43               // N_/256 weight tiles
#define NTILES (NT_ * MT_)   // 1376
#define FULLS  1332          // 148 * 9 full tiles
#define TAILT  (NTILES - FULLS)          // 44 leftover tiles, K-split across:
#define TAILW  148                       // 148 segment workers
#define GRID_GEMM (FULLS + TAILW)        // 1480

#define A_TILE_BYTES 16384   // 128 rows (m) x 128B (64 fp16 k)
#define W_TILE_BYTES 32768   // 256 rows (n) x 128B
#define STAGE_BYTES  (A_TILE_BYTES + W_TILE_BYTES)   // 49152
#define STAGES 4
#define OFF_CTRL   (STAGES * STAGE_BYTES)            // 196608
#define OFF_FULL   (OFF_CTRL)
#define OFF_DONE   (OFF_FULL + 8 * STAGES)
#define SMEM_TOTAL (OFF_CTRL + 128)

// merged prep kernel block ranges
#define PB_W 5504            // prep_w blocks (64 x 86)
#define PB_A 2048            // prep_a blocks (64 x 32)
#define PB_I TAILT           // tail-region bias-init blocks
#define GRID_PREP (PB_W + PB_A + PB_I)

#define SWZ(off) ((off) ^ (((off) >> 3) & 0x70))

// ---------------- scratch (static device arrays: allocation-free) ----------------
__device__ __align__(1024) __half g_w[(size_t)K_ * N_];   // ~90 MB, [nt][kc][swz 256x128B]
__device__ __align__(1024) __half g_a[(size_t)M_ * K_];   // ~32 MB, [mt][kc][swz 128x128B]

// ---------------- PTX helpers (base sm_103-safe) ----------------
__device__ __forceinline__ uint32_t smem_u32(const void* p) {
    uint32_t a;
    asm("{ .reg .u64 t; cvta.to.shared.u64 t, %1; cvt.u32.u64 %0, t; }" : "=r"(a) : "l"(p));
    return a;
}

#define MB_INIT(mbar, cnt) \
    asm volatile("mbarrier.init.shared.b64 [%0], %1;" :: "r"(mbar), "r"(cnt) : "memory")

#define MB_ARRIVE(mbar) \
    asm volatile("mbarrier.arrive.shared.b64 _, [%0];" :: "r"(mbar) : "memory")

#define MB_EXPECT_TX(mbar, bytes) \
    asm volatile("mbarrier.arrive.expect_tx.shared.b64 _, [%0], %1;" :: "r"(mbar), "r"(bytes) : "memory")

#define MB_WAIT(mbar, ph) do { \
    asm volatile("{\n\t.reg .pred P;\n\t" \
        "WL%=:\n\t" \
        "mbarrier.try_wait.parity.acquire.cta.shared::cta.b64 P, [%0], %1, 0x989680;\n\t" \
        "@P bra WD%=;\n\t" \
        "bra WL%=;\n\t" \
        "WD%=:\n\t}" :: "r"(mbar), "r"(ph) : "memory"); \
} while (0)

#define BULK_G2S(dst, src, bytes, mbar) \
    asm volatile("cp.async.bulk.shared::cluster.global.mbarrier::complete_tx::bytes [%0], [%1], %2, [%3];" \
        :: "r"(dst), "l"(src), "r"(bytes), "r"(mbar) : "memory")

#define LDSM4(r0, r1, r2, r3, addr) \
    asm volatile("ldmatrix.sync.aligned.m8n8.x4.shared.b16 {%0,%1,%2,%3}, [%4];" \
        : "=r"(r0), "=r"(r1), "=r"(r2), "=r"(r3) : "r"(addr))

#define MMA16816(acc, a0, a1, a2, a3, b0, b1) \
    asm volatile("mma.sync.aligned.m16n8k16.row.col.f32.f16.f16.f32 " \
        "{%0,%1,%2,%3}, {%4,%5,%6,%7}, {%8,%9}, {%0,%1,%2,%3};" \
        : "+f"((acc)[0]), "+f"((acc)[1]), "+f"((acc)[2]), "+f"((acc)[3]) \
        : "r"(a0), "r"(a1), "r"(a2), "r"(a3), "r"(b0), "r"(b1))

#define STG_CS_V4(ptr, r0, r1, r2, r3) \
    asm volatile("st.global.cs.v4.b32 [%0], {%1,%2,%3,%4};" \
        :: "l"(ptr), "r"(r0), "r"(r1), "r"(r2), "r"(r3) : "memory")

__device__ __forceinline__ unsigned pack2(float a, float b) {
    __half2 h = __floats2half2_rn(a, b);
    return *reinterpret_cast<unsigned*>(&h);
}

// ---------------- merged prep kernel ----------------
// bids [0, PB_W):            prep_w — int4 dequant + transpose -> fp16 256-row tiles
// bids [PB_W, PB_W+PB_A):    prep_a — fp32 -> fp16, 128-row tile panels + SW128
// bids [PB_W+PB_A, +PB_I):   init tail-tile output regions to bias (tail workers atomicAdd)
__global__ void prep_kernel(const float* __restrict__ in,
                            const int* __restrict__ q,
                            const float* __restrict__ sc,
                            const int* __restrict__ zp,
                            const float* __restrict__ bias,
                            float* __restrict__ out) {
    __shared__ int   qs[64 * 129];
    __shared__ float scs[128];
    __shared__ float zps[128];
    int bid = blockIdx.x, tid = threadIdx.x;

    if (bid < PB_W) {
        // ---------- prep_w ----------
        int kc = bid & 63, nt2 = bid >> 6;            // nt2 in [0,86)
        int nt = nt2 >> 1, half = nt2 & 1;
        int g = kc >> 1;                              // group of this 64-k chunk (G=128)
        if (tid < 128) {
            scs[tid] = sc[(size_t)g * N_ + nt2 * 128 + tid];
            zps[tid] = (float)zp[(size_t)g * N_ + nt2 * 128 + tid];
        }
#pragma unroll
        for (int it = 0; it < 8; it++) {
            int e4 = tid + it * 256;                  // 0..2047
            int kl = e4 >> 5;                         // row 0..63 (32 int4 per row)
            int nl4 = e4 & 31;
            int4 v = *(const int4*)(q + (size_t)(kc * 64 + kl) * N_ + nt2 * 128 + nl4 * 4);
            int* d = &qs[kl * 129 + nl4 * 4];
            d[0] = v.x; d[1] = v.y; d[2] = v.z; d[3] = v.w;
        }
        __syncthreads();

        char* dstbase = (char*)g_w + (size_t)(nt * KITERS + kc) * W_TILE_BYTES;
        int cc = tid & 7;
#pragma unroll
        for (int it = 0; it < 4; it++) {
            int r = (tid >> 3) + it * 32;             // 0..127 (n local within half)
            float s = scs[r], z = zps[r];
            unsigned u[4];
#pragma unroll
            for (int jj = 0; jj < 4; jj++) {
                int k0 = cc * 8 + jj * 2;
                float w0 = ((float)qs[(k0 + 0) * 129 + r] - z) * s;
                float w1 = ((float)qs[(k0 + 1) * 129 + r] - z) * s;
                u[jj] = pack2(w0, w1);
            }
            int row = half * 128 + r;                 // 0..255 (n local in tile)
            STG_CS_V4(dstbase + SWZ(row * 128 + cc * 16), u[0], u[1], u[2], u[3]);
        }
    } else if (bid < PB_W + PB_A) {
        // ---------- prep_a ----------
        int e = bid - PB_W;
        int kc = e & 63, mt = e >> 6;
        char* dstbase = (char*)g_a + (size_t)(mt * KITERS + kc) * A_TILE_BYTES;
        int cc = tid & 7;
#pragma unroll
        for (int it = 0; it < 4; it++) {
            int r = (tid >> 3) + it * 32;             // 0..127 (m local)
            int m = mt * 128 + r;
            int k0 = kc * 64 + cc * 8;
            const float4* p = (const float4*)(in + (size_t)m * K_ + k0);
            float4 f0 = p[0], f1 = p[1];
            uint4 v;
            v.x = pack2(f0.x, f0.y); v.y = pack2(f0.z, f0.w);
            v.z = pack2(f1.x, f1.y); v.w = pack2(f1.z, f1.w);
            *(uint4*)(dstbase + SWZ(r * 128 + cc * 16)) = v;
        }
    } else {
        // ---------- tail output init: out[region] = bias ----------
        int idx = bid - PB_W - PB_A;                  // 0..43
        int t = FULLS + idx;
        int nt = t >> 5, mt = t & 31;
        int row = tid >> 1, half = tid & 1;           // 128 rows x 2 column halves
        int m = mt * 128 + row;
        int n0 = nt * 256 + half * 128;
        float* po = out + (size_t)m * N_ + n0;
        const float4* bb = (const float4*)(bias + n0);
#pragma unroll
        for (int j = 0; j < 32; j++)
            *(float4*)(po + j * 4) = bb[j];
    }
}

// ---------------- GEMM body: CTA 128(M) x 256(N), warp tile 64x64, chunks [c0,c1) ----------------
// SEG=false: full tile (c0=0,c1=64), epilogue = streaming stores + bias
// SEG=true : K-segment of a tail tile, epilogue = atomicAdd (region pre-set to bias)
template<bool SEG>
__device__ __forceinline__ void gemm_body(
    uint32_t sb, const char* wsrc, const char* asrc,
    const float* __restrict__ bias, float* __restrict__ out,
    int nt, int mt, int c0, int c1)
{
    int tid = threadIdx.x, lane = tid & 31, wid = tid >> 5;
    int wm = wid & 1;          // 0..1  (64-row m half)
    int wn = wid >> 1;         // 0..3  (64-col n slice)
    int nch = c1 - c0;

    uint32_t mb_full = sb + OFF_FULL;
    uint32_t mb_done = sb + OFF_DONE;

    if (tid == 0) {
#pragma unroll
        for (int p = 0; p < STAGES; p++) {
            MB_EXPECT_TX(mb_full + 8 * p, (unsigned)STAGE_BYTES);
            BULK_G2S(sb + p * STAGE_BYTES,
                     wsrc + (size_t)(c0 + p) * W_TILE_BYTES, (unsigned)W_TILE_BYTES, mb_full + 8 * p);
            BULK_G2S(sb + p * STAGE_BYTES + W_TILE_BYTES,
                     asrc + (size_t)(c0 + p) * A_TILE_BYTES, (unsigned)A_TILE_BYTES, mb_full + 8 * p);
        }
    }

    // per-thread ldmatrix row bases (stage-relative)
    uint32_t a_roff[4], b_roff[4];
    uint32_t a_swz[4], b_swz[4];
#pragma unroll
    for (int mi = 0; mi < 4; mi++) {
        int row = wm * 64 + mi * 16 + (lane & 15);
        a_roff[mi] = W_TILE_BYTES + row * 128;        // A sits after W in stage
        a_swz[mi] = row & 7;
    }
#pragma unroll
    for (int nb = 0; nb < 4; nb++) {
        int row = wn * 64 + nb * 16 + (lane & 7) + ((lane >> 4) << 3);
        b_roff[nb] = row * 128;
        b_swz[nb] = row & 7;
    }
    uint32_t a_c = (lane >> 4);        // 0..1, A k-half within 16B cols
    uint32_t b_c = (lane >> 3) & 1;    // 0..1, B k-half

    float acc[4][8][4];
#pragma unroll
    for (int mi = 0; mi < 4; mi++)
#pragma unroll
        for (int ni = 0; ni < 8; ni++)
#pragma unroll
            for (int e = 0; e < 4; e++) acc[mi][ni][e] = 0.f;

#pragma unroll 1
    for (int r = 0; r < nch; r++) {
        int s = r & (STAGES - 1);
        MB_WAIT(mb_full + 8 * s, (r >> 2) & 1);
        uint32_t stg = sb + s * STAGE_BYTES;
#pragma unroll
        for (int ks = 0; ks < 4; ks++) {
            uint32_t a[4][4], b[4][4];
#pragma unroll
            for (int mi = 0; mi < 4; mi++) {
                uint32_t addr = stg + a_roff[mi] + (((ks * 2 + a_c) ^ a_swz[mi]) << 4);
                LDSM4(a[mi][0], a[mi][1], a[mi][2], a[mi][3], addr);
            }
#pragma unroll
            for (int nb = 0; nb < 4; nb++) {
                uint32_t addr = stg + b_roff[nb] + (((ks * 2 + b_c) ^ b_swz[nb]) << 4);
                LDSM4(b[nb][0], b[nb][1], b[nb][2], b[nb][3], addr);
            }
#pragma unroll
            for (int mi = 0; mi < 4; mi++)
#pragma unroll
                for (int ni = 0; ni < 8; ni++)
                    MMA16816(acc[mi][ni],
                             a[mi][0], a[mi][1], a[mi][2], a[mi][3],
                             b[ni >> 1][(ni & 1) * 2], b[ni >> 1][(ni & 1) * 2 + 1]);
        }
        if (lane == 0) MB_ARRIVE(mb_done + 8 * s);
        if (tid == 0 && r + STAGES < nch) {
            MB_WAIT(mb_done + 8 * s, (r >> 2) & 1);   // all 8 warps done with this stage
            MB_EXPECT_TX(mb_full + 8 * s, (unsigned)STAGE_BYTES);
            BULK_G2S(sb + s * STAGE_BYTES,
                     wsrc + (size_t)(c0 + r + STAGES) * W_TILE_BYTES, (unsigned)W_TILE_BYTES, mb_full + 8 * s);
            BULK_G2S(sb + s * STAGE_BYTES + W_TILE_BYTES,
                     asrc + (size_t)(c0 + r + STAGES) * A_TILE_BYTES, (unsigned)A_TILE_BYTES, mb_full + 8 * s);
        }
    }

    // ---- epilogue ----
    int m0 = mt * 128 + wm * 64 + (lane >> 2);
    int n0 = nt * 256 + wn * 64 + (lane & 3) * 2;
    if (SEG) {
        // partial K-sum: accumulate into bias-initialized region
#pragma unroll
        for (int ni = 0; ni < 8; ni++) {
            int n = n0 + ni * 8;
#pragma unroll
            for (int mi = 0; mi < 4; mi++) {
                int m = m0 + mi * 16;
                atomicAdd(out + (size_t)m * N_ + n,     acc[mi][ni][0]);
                atomicAdd(out + (size_t)m * N_ + n + 1, acc[mi][ni][1]);
                atomicAdd(out + (size_t)(m + 8) * N_ + n,     acc[mi][ni][2]);
                atomicAdd(out + (size_t)(m + 8) * N_ + n + 1, acc[mi][ni][3]);
            }
        }
    } else {
#pragma unroll
        for (int ni = 0; ni < 8; ni++) {
            int n = n0 + ni * 8;
            float2 bb = *(const float2*)(bias + n);
#pragma unroll
            for (int mi = 0; mi < 4; mi++) {
                int m = m0 + mi * 16;
                float2 v0 = make_float2(acc[mi][ni][0] + bb.x, acc[mi][ni][1] + bb.y);
                float2 v1 = make_float2(acc[mi][ni][2] + bb.x, acc[mi][ni][3] + bb.y);
                __stcs((float2*)(out + (size_t)m * N_ + n), v0);
                __stcs((float2*)(out + (size_t)(m + 8) * N_ + n), v1);
            }
        }
    }
}

// ---------------- GEMM kernel: 1332 full tiles + 148 K-segment tail workers ----------------
// grid GRID_GEMM, 256 threads (8 warps), dyn smem SMEM_TOTAL
__global__ void __launch_bounds__(256, 1)
gemm_kernel(const float* __restrict__ bias, float* __restrict__ out) {
    extern __shared__ char smem[];
    uint32_t sb = smem_u32(smem);
    int tid = threadIdx.x;
    int bid = blockIdx.x;

    uint32_t mb_full = sb + OFF_FULL;
    uint32_t mb_done = sb + OFF_DONE;
    if (tid == 0) {
        for (int s = 0; s < STAGES; s++) { MB_INIT(mb_full + 8 * s, 1); MB_INIT(mb_done + 8 * s, 8); }
    }
    __syncthreads();

    if (bid < FULLS) {
        int t = bid;
        int nt = t >> 5, mt = t & 31;     // 32 consecutive bids share one W panel (L2 reuse)
        const char* wsrc = (const char*)g_w + (size_t)nt * KITERS * W_TILE_BYTES;
        const char* asrc = (const char*)g_a + (size_t)mt * KITERS * A_TILE_BYTES;
        gemm_body<false>(sb, wsrc, asrc, bias, out, nt, mt, 0, KITERS);
    } else {
        int w = bid - FULLS;              // 0..147
        int j = w % TAILT;                // tail tile 0..43
        int r = w / TAILT;                // worker index within tile (0..3)
        int nw = (j < (TAILW - 3 * TAILT)) ? 4 : 3;   // tiles 0..15 get 4 workers, rest 3
        int c0 = (KITERS * r) / nw;
        int c1 = (KITERS * (r + 1)) / nw;
        int t = FULLS + j;
        int nt = t >> 5, mt = t & 31;
        const char* wsrc = (const char*)g_w + (size_t)nt * KITERS * W_TILE_BYTES;
        const char* asrc = (const char*)g_a + (size_t)mt * KITERS * A_TILE_BYTES;
        gemm_body<true>(sb, wsrc, asrc, bias, out, nt, mt, c0, c1);
    }
}

// ---------------- launch ----------------
extern "C" void kernel_launch(void* const* d_in, const int* in_sizes, int n_in,
                              void* d_out, int out_size) {
    const float* input   = (const float*)d_in[0];
    const int*   qweight = (const int*)d_in[1];
    const float* scales  = (const float*)d_in[2];
    const int*   qzeros  = (const int*)d_in[3];
    const float* bias    = (const float*)d_in[4];
    float* out = (float*)d_out;

    cudaFuncSetAttribute(gemm_kernel, cudaFuncAttributeMaxDynamicSharedMemorySize, SMEM_TOTAL);

    prep_kernel<<<GRID_PREP, 256>>>(input, qweight, scales, qzeros, bias, out);
    gemm_kernel<<<GRID_GEMM, 256, SMEM_TOTAL>>>(bias, out);
}